// round 1
// baseline (speedup 1.0000x reference)
#include <cuda_runtime.h>

#define BATCH 1024
#define D_IN 3072
#define R_HID 128
#define NEXP 8
#define E_HID 2048
#define N_CLS 10
#define TB 16   // samples per expert-tile

// Scratch: per-expert routing buckets (device globals — no allocation)
__device__ int   g_cnt[NEXP];
__device__ int   g_lb[NEXP][BATCH];
__device__ float g_lw[NEXP][BATCH];

__global__ void k_init(float* out) {
    int i = blockIdx.x * blockDim.x + threadIdx.x;
    if (i < BATCH * N_CLS) out[i] = 0.f;
    if (i < NEXP) g_cnt[i] = 0;
}

// Router: 128 blocks x 128 threads, 8 samples/block.
// rh = relu(x @ rW1 + rb1); logits = rh @ rW2 + rb2; softmax -> top2 -> renorm.
__global__ void k_router(const float* __restrict__ x,
                         const float* __restrict__ rW1, const float* __restrict__ rb1,
                         const float* __restrict__ rW2, const float* __restrict__ rb2) {
    __shared__ float sX[8][512];
    __shared__ float sRh[8][R_HID];
    __shared__ float sLog[8][NEXP];
    const int tid = threadIdx.x;
    const int b0 = blockIdx.x * 8;

    float acc[8];
#pragma unroll
    for (int s = 0; s < 8; s++) acc[s] = 0.f;

    for (int kt = 0; kt < D_IN / 512; kt++) {
        __syncthreads();
        for (int i = tid; i < 8 * 512; i += 128) {
            int s = i >> 9, d = i & 511;
            sX[s][d] = x[(size_t)(b0 + s) * D_IN + kt * 512 + d];
        }
        __syncthreads();
#pragma unroll 4
        for (int d = 0; d < 512; d++) {
            float w = rW1[(size_t)(kt * 512 + d) * R_HID + tid];
#pragma unroll
            for (int s = 0; s < 8; s++) acc[s] = fmaf(sX[s][d], w, acc[s]);
        }
    }
    __syncthreads();
    float bias = rb1[tid];
#pragma unroll
    for (int s = 0; s < 8; s++) sRh[s][tid] = fmaxf(acc[s] + bias, 0.f);
    __syncthreads();

    if (tid < 64) {
        int s = tid >> 3, e = tid & 7;
        float l = rb2[e];
#pragma unroll 8
        for (int j = 0; j < R_HID; j++) l = fmaf(sRh[s][j], rW2[j * NEXP + e], l);
        sLog[s][e] = l;
    }
    __syncthreads();

    if (tid < 8) {
        int s = tid;
        // top-1 (strict > keeps smallest index on ties, matching jax top_k)
        int e0 = 0; float l0 = sLog[s][0];
        for (int e = 1; e < NEXP; e++) { float v = sLog[s][e]; if (v > l0) { l0 = v; e0 = e; } }
        // top-2
        int e1 = (e0 == 0) ? 1 : 0; float l1 = sLog[s][e1];
        for (int e = 0; e < NEXP; e++) {
            if (e == e0) continue;
            float v = sLog[s][e]; if (v > l1) { l1 = v; e1 = e; }
        }
        // renormalized top-2 softmax weights: w0 = e^l0/(e^l0+e^l1)
        float w0 = 1.f / (1.f + expf(l1 - l0));
        float w1 = 1.f - w0;
        int b = b0 + s;
        int p0 = atomicAdd(&g_cnt[e0], 1); g_lb[e0][p0] = b; g_lw[e0][p0] = w0;
        int p1 = atomicAdd(&g_cnt[e1], 1); g_lb[e1][p1] = b; g_lw[e1][p1] = w1;
    }
}

// Expert GEMM + fused second GEMM.
// grid: (BATCH/TB tiles, NEXP experts, 2 h-halves), 256 threads.
// Thread map: hx = tid&15 owns 8 consecutive h; by = tid>>4 owns 1 sample.
__global__ void __launch_bounds__(256) k_expert(
    const float* __restrict__ x,
    const float* __restrict__ eW1, const float* __restrict__ eb1,
    const float* __restrict__ eW2, const float* __restrict__ eb2,
    float* __restrict__ out)
{
    const int e = blockIdx.y;
    const int z = blockIdx.z;           // h half: [z*1024, z*1024+1024)
    const int n = g_cnt[e];
    const int start = blockIdx.x * TB;
    if (start >= n) return;

    __shared__ float sX[TB][256];
    __shared__ int   sB[TB];
    __shared__ float sW[TB];
    __shared__ float sRed[256][N_CLS];

    const int tid = threadIdx.x;
    if (tid < TB) {
        int i = start + tid;
        if (i < n) { sB[tid] = g_lb[e][i]; sW[tid] = g_lw[e][i]; }
        else       { sB[tid] = g_lb[e][start]; sW[tid] = 0.f; }   // padded lane, weight 0
    }
    __syncthreads();

    const int hx = tid & 15;
    const int by = tid >> 4;
    const size_t w1base = (size_t)e * D_IN * E_HID;

    float outAcc[N_CLS];
#pragma unroll
    for (int c = 0; c < N_CLS; c++) outAcc[c] = (z == 0) ? eb2[e * N_CLS + c] : 0.f;

    for (int hc = 0; hc < 8; hc++) {
        const int h0 = z * 1024 + hc * 128 + hx * 8;
        float acc[8] = {0.f, 0.f, 0.f, 0.f, 0.f, 0.f, 0.f, 0.f};

        for (int kt = 0; kt < D_IN / 256; kt++) {
            __syncthreads();   // guard previous sX use
#pragma unroll
            for (int i = tid; i < TB * 256; i += 256) {
                int s = i >> 8, d = i & 255;
                sX[s][d] = x[(size_t)sB[s] * D_IN + kt * 256 + d];
            }
            __syncthreads();

            const float* wp = eW1 + w1base + (size_t)(kt * 256) * E_HID + h0;
            const float* xs = sX[by];
#pragma unroll 4
            for (int d = 0; d < 256; d++) {
                float4 wa = *(const float4*)(wp);
                float4 wb = *(const float4*)(wp + 4);
                float xv = xs[d];
                acc[0] = fmaf(xv, wa.x, acc[0]);
                acc[1] = fmaf(xv, wa.y, acc[1]);
                acc[2] = fmaf(xv, wa.z, acc[2]);
                acc[3] = fmaf(xv, wa.w, acc[3]);
                acc[4] = fmaf(xv, wb.x, acc[4]);
                acc[5] = fmaf(xv, wb.y, acc[5]);
                acc[6] = fmaf(xv, wb.z, acc[6]);
                acc[7] = fmaf(xv, wb.w, acc[7]);
                wp += E_HID;
            }
        }
        // epilogue for this 8-h slice: bias + relu + second GEMM into out accumulator
#pragma unroll
        for (int i = 0; i < 8; i++) {
            int h = h0 + i;
            float v = fmaxf(acc[i] + eb1[e * E_HID + h], 0.f);
#pragma unroll
            for (int c = 0; c < N_CLS; c++)
                outAcc[c] = fmaf(v, eW2[((size_t)e * E_HID + h) * N_CLS + c], outAcc[c]);
        }
    }

    // reduce over the 16 hx threads owning the same sample
    __syncthreads();
#pragma unroll
    for (int c = 0; c < N_CLS; c++) sRed[tid][c] = outAcc[c];
    __syncthreads();
    if (tid < TB * N_CLS) {
        int s = tid / N_CLS, c = tid % N_CLS;
        float t = 0.f;
#pragma unroll
        for (int h2 = 0; h2 < 16; h2++) t += sRed[h2 + 16 * s][c];
        atomicAdd(&out[(size_t)sB[s] * N_CLS + c], sW[s] * t);
    }
}

extern "C" void kernel_launch(void* const* d_in, const int* in_sizes, int n_in,
                              void* d_out, int out_size) {
    const float* x   = (const float*)d_in[0];
    const float* rW1 = (const float*)d_in[1];
    const float* rb1 = (const float*)d_in[2];
    const float* rW2 = (const float*)d_in[3];
    const float* rb2 = (const float*)d_in[4];
    const float* eW1 = (const float*)d_in[5];
    const float* eb1 = (const float*)d_in[6];
    const float* eW2 = (const float*)d_in[7];
    const float* eb2 = (const float*)d_in[8];
    float* out = (float*)d_out;

    k_init<<<(BATCH * N_CLS + 255) / 256, 256>>>(out);
    k_router<<<BATCH / 8, 128>>>(x, rW1, rb1, rW2, rb2);
    dim3 g(BATCH / TB, NEXP, 2);
    k_expert<<<g, 256>>>(x, eW1, eb1, eW2, eb2, out);
}

// round 2
// speedup vs baseline: 16.0084x; 16.0084x over previous
#include <cuda_runtime.h>

#define BATCH 1024
#define D_IN 3072
#define R_HID 128
#define NEXP 8
#define E_HID 2048
#define N_CLS 10

// Routing buckets (device globals — no allocation)
__device__ int   g_cnt[NEXP];
__device__ int   g_lb[NEXP][BATCH];
__device__ float g_lw[NEXP][BATCH];

__global__ void k_init() {
    if (threadIdx.x < NEXP) g_cnt[threadIdx.x] = 0;
}

// Router: 128 blocks x 128 threads, 8 samples/block.
// Also writes the routing-weighted eb2 bias directly into out (sole writer
// of out before expert atomics).
__global__ void k_router(const float* __restrict__ x,
                         const float* __restrict__ rW1, const float* __restrict__ rb1,
                         const float* __restrict__ rW2, const float* __restrict__ rb2,
                         const float* __restrict__ eb2, float* __restrict__ out) {
    __shared__ float sX[8][512];
    __shared__ float sRh[8][R_HID];
    __shared__ float sLog[8][NEXP];
    const int tid = threadIdx.x;
    const int b0 = blockIdx.x * 8;

    float acc[8];
#pragma unroll
    for (int s = 0; s < 8; s++) acc[s] = 0.f;

    for (int kt = 0; kt < D_IN / 512; kt++) {
        __syncthreads();
        for (int i = tid; i < 8 * 512; i += 128) {
            int s = i >> 9, d = i & 511;
            sX[s][d] = x[(size_t)(b0 + s) * D_IN + kt * 512 + d];
        }
        __syncthreads();
#pragma unroll 4
        for (int d = 0; d < 512; d++) {
            float w = rW1[(size_t)(kt * 512 + d) * R_HID + tid];
#pragma unroll
            for (int s = 0; s < 8; s++) acc[s] = fmaf(sX[s][d], w, acc[s]);
        }
    }
    __syncthreads();
    float bias = rb1[tid];
#pragma unroll
    for (int s = 0; s < 8; s++) sRh[s][tid] = fmaxf(acc[s] + bias, 0.f);
    __syncthreads();

    if (tid < 64) {
        int s = tid >> 3, e = tid & 7;
        float l = rb2[e];
#pragma unroll 8
        for (int j = 0; j < R_HID; j++) l = fmaf(sRh[s][j], rW2[j * NEXP + e], l);
        sLog[s][e] = l;
    }
    __syncthreads();

    if (tid < 8) {
        int s = tid;
        int e0 = 0; float l0 = sLog[s][0];
        for (int e = 1; e < NEXP; e++) { float v = sLog[s][e]; if (v > l0) { l0 = v; e0 = e; } }
        int e1 = (e0 == 0) ? 1 : 0; float l1 = sLog[s][e1];
        for (int e = 0; e < NEXP; e++) {
            if (e == e0) continue;
            float v = sLog[s][e]; if (v > l1) { l1 = v; e1 = e; }
        }
        float w0 = 1.f / (1.f + expf(l1 - l0));
        float w1 = 1.f - w0;
        int b = b0 + s;
        // init out with routing-weighted expert-2 biases
#pragma unroll
        for (int c = 0; c < N_CLS; c++)
            out[(size_t)b * N_CLS + c] = w0 * eb2[e0 * N_CLS + c] + w1 * eb2[e1 * N_CLS + c];
        int p0 = atomicAdd(&g_cnt[e0], 1); g_lb[e0][p0] = b; g_lw[e0][p0] = w0;
        int p1 = atomicAdd(&g_cnt[e1], 1); g_lb[e1][p1] = b; g_lw[e1][p1] = w1;
    }
}

__device__ __forceinline__ unsigned f2tf(float f) {
    unsigned u; asm("cvt.rna.tf32.f32 %0, %1;" : "=r"(u) : "f"(f)); return u;
}

#define MMA_TF32(acc, af, bf)                                                   \
    asm volatile("mma.sync.aligned.m16n8k8.row.col.f32.tf32.tf32.f32 "          \
                 "{%0,%1,%2,%3},{%4,%5,%6,%7},{%8,%9},{%0,%1,%2,%3};"           \
                 : "+f"(acc[0]), "+f"(acc[1]), "+f"(acc[2]), "+f"(acc[3])       \
                 : "r"(af[0]), "r"(af[1]), "r"(af[2]), "r"(af[3]),              \
                   "r"(bf[0]), "r"(bf[1]));

// Expert GEMM (tf32 tensor cores) + fused relu + second GEMM.
// grid: (16 max M-tiles, 8 experts, 32 h-tiles), 256 threads = 8 warps (2M x 4N).
// Block tile: 64 tokens x 64 h, K staged 32 at a time, double-buffered.
__global__ void __launch_bounds__(256) k_expert(
    const float* __restrict__ x,
    const float* __restrict__ eW1, const float* __restrict__ eb1,
    const float* __restrict__ eW2, float* __restrict__ out)
{
    const int e = blockIdx.y;
    const int z = blockIdx.z;            // h tile: [z*64, z*64+64)
    const int n = g_cnt[e];
    const int start = blockIdx.x * 64;
    if (start >= n) return;

    // A: [64][36] swizzle stride (bank = 4*quad+qt perm), B: [32][72] (bank = 8*qt+quad perm)
    __shared__ union {
        struct { unsigned A[2][64 * 36]; unsigned B[2][32 * 72]; } mm;
        float eh[64][68];
    } sm;
    __shared__ int   sTok[64];
    __shared__ float sWt[64];

    const int tid  = threadIdx.x;
    const int lane = tid & 31, wid = tid >> 5;
    const int quad = lane >> 2, qt = lane & 3;
    const int warpM = wid & 1, warpN = wid >> 1;

    if (tid < 64) {
        int i = start + tid;
        if (i < n) { sTok[tid] = g_lb[e][i]; sWt[tid] = g_lw[e][i]; }
        else       { sTok[tid] = g_lb[e][start]; sWt[tid] = 0.f; }
    }
    __syncthreads();

    // Static staging assignment (2 float4 of A, 2 float4 of B per thread per stage)
    const int fA1 = tid + 256;
    const int mA0 = tid >> 3, kA0 = (tid & 7) * 4;
    const int mA1 = fA1 >> 3, kA1 = (fA1 & 7) * 4;
    const size_t tok0 = (size_t)sTok[mA0], tok1 = (size_t)sTok[mA1];
    const int rB0 = tid >> 4, nB0 = (tid & 15) * 4;
    const int rB1 = fA1 >> 4, nB1 = (fA1 & 15) * 4;
    const float* w1p = eW1 + (size_t)e * D_IN * E_HID + (size_t)z * 64;

    float4 a0v, a1v, b0v, b1v;
    a0v = *(const float4*)&x[tok0 * D_IN + kA0];
    a1v = *(const float4*)&x[tok1 * D_IN + kA1];
    b0v = *(const float4*)&w1p[(size_t)rB0 * E_HID + nB0];
    b1v = *(const float4*)&w1p[(size_t)rB1 * E_HID + nB1];

    float acc[2][2][4];
#pragma unroll
    for (int mt = 0; mt < 2; mt++)
#pragma unroll
        for (int nt = 0; nt < 2; nt++)
#pragma unroll
            for (int i = 0; i < 4; i++) acc[mt][nt][i] = 0.f;

    int buf = 0;
#pragma unroll 1
    for (int s = 0; s < D_IN / 32; s++) {
        {
            unsigned* A  = sm.mm.A[buf];
            unsigned* Bm = sm.mm.B[buf];
            uint4 t;
            t.x = f2tf(a0v.x); t.y = f2tf(a0v.y); t.z = f2tf(a0v.z); t.w = f2tf(a0v.w);
            *(uint4*)&A[mA0 * 36 + kA0] = t;
            t.x = f2tf(a1v.x); t.y = f2tf(a1v.y); t.z = f2tf(a1v.z); t.w = f2tf(a1v.w);
            *(uint4*)&A[mA1 * 36 + kA1] = t;
            t.x = f2tf(b0v.x); t.y = f2tf(b0v.y); t.z = f2tf(b0v.z); t.w = f2tf(b0v.w);
            *(uint4*)&Bm[rB0 * 72 + nB0] = t;
            t.x = f2tf(b1v.x); t.y = f2tf(b1v.y); t.z = f2tf(b1v.z); t.w = f2tf(b1v.w);
            *(uint4*)&Bm[rB1 * 72 + nB1] = t;
        }
        __syncthreads();

        if (s + 1 < D_IN / 32) {
            int k0g = (s + 1) * 32;
            a0v = *(const float4*)&x[tok0 * D_IN + k0g + kA0];
            a1v = *(const float4*)&x[tok1 * D_IN + k0g + kA1];
            b0v = *(const float4*)&w1p[(size_t)(k0g + rB0) * E_HID + nB0];
            b1v = *(const float4*)&w1p[(size_t)(k0g + rB1) * E_HID + nB1];
        }

        const unsigned* A  = sm.mm.A[buf];
        const unsigned* Bm = sm.mm.B[buf];
#pragma unroll
        for (int ks = 0; ks < 4; ks++) {
            const int kq = ks * 8 + qt;
            unsigned af[2][4], bf[2][2];
#pragma unroll
            for (int mt = 0; mt < 2; mt++) {
                int r = warpM * 32 + mt * 16 + quad;
                af[mt][0] = A[r * 36 + kq];
                af[mt][1] = A[(r + 8) * 36 + kq];
                af[mt][2] = A[r * 36 + kq + 4];
                af[mt][3] = A[(r + 8) * 36 + kq + 4];
            }
#pragma unroll
            for (int nt = 0; nt < 2; nt++) {
                int c = warpN * 16 + nt * 8 + quad;
                bf[nt][0] = Bm[kq * 72 + c];
                bf[nt][1] = Bm[(kq + 4) * 72 + c];
            }
#pragma unroll
            for (int mt = 0; mt < 2; mt++)
#pragma unroll
                for (int nt = 0; nt < 2; nt++)
                    MMA_TF32(acc[mt][nt], af[mt], bf[nt]);
        }
        buf ^= 1;
    }

    // Epilogue: bias + relu into smem eh tile (aliases A/B buffers)
    __syncthreads();
    const float* b1p = eb1 + (size_t)e * E_HID + (size_t)z * 64;
#pragma unroll
    for (int mt = 0; mt < 2; mt++) {
#pragma unroll
        for (int nt = 0; nt < 2; nt++) {
            int r = warpM * 32 + mt * 16 + quad;
            int c = warpN * 16 + nt * 8 + qt * 2;
            float vb0 = b1p[c], vb1 = b1p[c + 1];
            sm.eh[r][c]         = fmaxf(acc[mt][nt][0] + vb0, 0.f);
            sm.eh[r][c + 1]     = fmaxf(acc[mt][nt][1] + vb1, 0.f);
            sm.eh[r + 8][c]     = fmaxf(acc[mt][nt][2] + vb0, 0.f);
            sm.eh[r + 8][c + 1] = fmaxf(acc[mt][nt][3] + vb1, 0.f);
        }
    }
    __syncthreads();

    // Second GEMM: out[tok][c] += w_tok * sum_h eh[tok][h] * eW2[e][z*64+h][c]
    for (int idx = tid; idx < 64 * N_CLS; idx += 256) {
        int t = idx / N_CLS, c = idx % N_CLS;
        float wgt = sWt[t];
        if (wgt != 0.f) {
            const float* w2p = eW2 + ((size_t)e * E_HID + (size_t)z * 64) * N_CLS + c;
            float s0 = 0.f, s1 = 0.f, s2 = 0.f, s3 = 0.f;
#pragma unroll
            for (int h = 0; h < 64; h += 4) {
                s0 = fmaf(sm.eh[t][h],     w2p[(h)     * N_CLS], s0);
                s1 = fmaf(sm.eh[t][h + 1], w2p[(h + 1) * N_CLS], s1);
                s2 = fmaf(sm.eh[t][h + 2], w2p[(h + 2) * N_CLS], s2);
                s3 = fmaf(sm.eh[t][h + 3], w2p[(h + 3) * N_CLS], s3);
            }
            atomicAdd(&out[(size_t)sTok[t] * N_CLS + c], wgt * ((s0 + s1) + (s2 + s3)));
        }
    }
}

extern "C" void kernel_launch(void* const* d_in, const int* in_sizes, int n_in,
                              void* d_out, int out_size) {
    const float* x   = (const float*)d_in[0];
    const float* rW1 = (const float*)d_in[1];
    const float* rb1 = (const float*)d_in[2];
    const float* rW2 = (const float*)d_in[3];
    const float* rb2 = (const float*)d_in[4];
    const float* eW1 = (const float*)d_in[5];
    const float* eb1 = (const float*)d_in[6];
    const float* eW2 = (const float*)d_in[7];
    const float* eb2 = (const float*)d_in[8];
    float* out = (float*)d_out;

    k_init<<<1, 32>>>();
    k_router<<<BATCH / 8, 128>>>(x, rW1, rb1, rW2, rb2, eb2, out);
    dim3 g(16, NEXP, E_HID / 64);
    k_expert<<<g, 256>>>(x, eW1, eb1, eW2, out);
}